// round 10
// baseline (speedup 1.0000x reference)
#include <cuda_runtime.h>
#include <cuda_bf16.h>
#include <math.h>

#define N_NODES   100000
#define N_EDGES   1600000
#define IN_CH     128
#define HID       64
#define OUT_CH    10
#define NGRAPH    256

// -------- scratch (device globals: no runtime allocation) --------
__device__ __align__(16) float g_h[N_NODES * HID];     // 25.6 MB, holds h*dinv[row]
__device__ __align__(16) float g_agg[N_NODES * HID];   // 25.6 MB
__device__ __align__(16) float g_dinv[N_NODES];
__device__ __align__(16) int   g_deg[N_NODES];
__device__ __align__(16) float g_pooled[NGRAPH * HID];
__device__ __align__(16) float g_cnt[NGRAPH];
__device__ int g_is64;

// -------- 1. zero small scratch (deg, pooled, cnt) + detect index width ---
// g_agg zeroing is folded into the GEMM epilogue (each row visited once).
// Width probe: indices are uniform in [0, 100000) < 2^31. If little-endian
// int64, every high 32-bit word is 0. If int32, those words are random
// indices; P(all 64 zero) = (1e-5)^64 ~ 0.
__global__ void zero_kernel(const unsigned int* __restrict__ e) {
    int i = blockIdx.x * blockDim.x + threadIdx.x;   // 25088 threads
    float4 z = make_float4(0.f, 0.f, 0.f, 0.f);
    if (i < N_NODES / 4)         reinterpret_cast<int4*>(g_deg)[i]   = make_int4(0, 0, 0, 0);
    if (i < (NGRAPH * HID) / 4)  reinterpret_cast<float4*>(g_pooled)[i] = z;
    if (i < NGRAPH / 4)          reinterpret_cast<float4*>(g_cnt)[i] = z;
    if (i == 0) {
        int all0 = 1;
        #pragma unroll
        for (int k = 0; k < 64; k++) {
            if (e[2 * k + 1] != 0u) { all0 = 0; break; }
        }
        g_is64 = all0;
    }
}

// -------- 2. in-degree over dst (4 edges/thread, vector index loads) ------
__global__ void degree_kernel(const void* __restrict__ eidx) {
    int i = blockIdx.x * blockDim.x + threadIdx.x;  // i indexes groups of 4
    if (i >= N_EDGES / 4) return;
    if (g_is64) {
        const longlong2* p = (const longlong2*)eidx + N_EDGES / 2;  // dst base
        longlong2 a = __ldg(p + 2 * i);
        longlong2 b = __ldg(p + 2 * i + 1);
        atomicAdd(&g_deg[(int)a.x], 1);
        atomicAdd(&g_deg[(int)a.y], 1);
        atomicAdd(&g_deg[(int)b.x], 1);
        atomicAdd(&g_deg[(int)b.y], 1);
    } else {
        const int4* p = (const int4*)eidx + N_EDGES / 4;            // dst base
        int4 a = __ldg(p + i);
        atomicAdd(&g_deg[a.x], 1);
        atomicAdd(&g_deg[a.y], 1);
        atomicAdd(&g_deg[a.z], 1);
        atomicAdd(&g_deg[a.w], 1);
    }
}

// -------- 3. dinv = rsqrt(deg + self_loop), 4 nodes/thread ----------------
__global__ void dinv_kernel() {
    int i = blockIdx.x * blockDim.x + threadIdx.x;   // groups of 4 nodes
    if (i >= N_NODES / 4) return;
    int4 d = reinterpret_cast<const int4*>(g_deg)[i];
    float4 r;
    r.x = rsqrtf((float)(d.x + 1));
    r.y = rsqrtf((float)(d.y + 1));
    r.z = rsqrtf((float)(d.z + 1));
    r.w = rsqrtf((float)(d.w + 1));
    reinterpret_cast<float4*>(g_dinv)[i] = r;
}

// -------- 4. h' = (x @ W_conv) * dinv[row]; also zero g_agg row ----------
// Block = (16,16): ty -> row (16 rows/block), tx -> 4 output channels.
// Per 4 k-steps: 4x LDS.128 (W) + 1x LDS.128 (x) + 16 FFMA = 1.31 issues/FMA.
// 100000/16 = 6250 blocks exactly: no bounds checks needed.
// The dinv row-scale is folded into the epilogue so the scatter only needs
// dinv[dst] and pooling only needs one extra multiply. The epilogue also
// zero-fills this thread's float4 of g_agg (saves a dedicated 25.6MB pass).
__global__ __launch_bounds__(256) void gemm1_kernel(const float* __restrict__ x,
                                                    const float* __restrict__ W) {
    __shared__ __align__(16) float Ws[IN_CH * HID];   // 32 KB, [k][ch]
    __shared__ __align__(16) float xs[16][IN_CH];     // 8 KB

    const int tx = threadIdx.x;          // 0..15 -> channels 4*tx..4*tx+3
    const int ty = threadIdx.y;          // 0..15 -> row within block
    const int tid = ty * 16 + tx;

    // stage W (same layout as global: W[k*HID+ch])
    #pragma unroll
    for (int i = 0; i < 8; i++)
        reinterpret_cast<float4*>(Ws)[tid + i * 256] =
            reinterpret_cast<const float4*>(W)[tid + i * 256];

    // stage 16 rows of x: each thread 2 float4 of its ty row
    {
        const size_t rowOff = ((size_t)blockIdx.x * 16 + ty) * IN_CH;
        reinterpret_cast<float4*>(&xs[ty][0])[tx * 2] =
            reinterpret_cast<const float4*>(x + rowOff)[tx * 2];
        reinterpret_cast<float4*>(&xs[ty][0])[tx * 2 + 1] =
            reinterpret_cast<const float4*>(x + rowOff)[tx * 2 + 1];
    }
    __syncthreads();

    float4 acc = make_float4(0.f, 0.f, 0.f, 0.f);
    #pragma unroll
    for (int k = 0; k < IN_CH; k += 4) {
        float4 xv = *reinterpret_cast<const float4*>(&xs[ty][k]);
        float4 w0 = *reinterpret_cast<const float4*>(&Ws[(k + 0) * HID + 4 * tx]);
        float4 w1 = *reinterpret_cast<const float4*>(&Ws[(k + 1) * HID + 4 * tx]);
        float4 w2 = *reinterpret_cast<const float4*>(&Ws[(k + 2) * HID + 4 * tx]);
        float4 w3 = *reinterpret_cast<const float4*>(&Ws[(k + 3) * HID + 4 * tx]);
        acc.x = fmaf(xv.x, w0.x, acc.x); acc.y = fmaf(xv.x, w0.y, acc.y);
        acc.z = fmaf(xv.x, w0.z, acc.z); acc.w = fmaf(xv.x, w0.w, acc.w);
        acc.x = fmaf(xv.y, w1.x, acc.x); acc.y = fmaf(xv.y, w1.y, acc.y);
        acc.z = fmaf(xv.y, w1.z, acc.z); acc.w = fmaf(xv.y, w1.w, acc.w);
        acc.x = fmaf(xv.z, w2.x, acc.x); acc.y = fmaf(xv.z, w2.y, acc.y);
        acc.z = fmaf(xv.z, w2.z, acc.z); acc.w = fmaf(xv.z, w2.w, acc.w);
        acc.x = fmaf(xv.w, w3.x, acc.x); acc.y = fmaf(xv.w, w3.y, acc.y);
        acc.z = fmaf(xv.w, w3.z, acc.z); acc.w = fmaf(xv.w, w3.w, acc.w);
    }

    const size_t row = (size_t)blockIdx.x * 16 + ty;
    const float di = g_dinv[row];
    acc.x *= di; acc.y *= di; acc.z *= di; acc.w *= di;
    reinterpret_cast<float4*>(g_h + row * HID)[tx] = acc;
    reinterpret_cast<float4*>(g_agg + row * HID)[tx] =
        make_float4(0.f, 0.f, 0.f, 0.f);
}

// -------- 5. edge scatter: agg[dst] += h'[src] * dinv[dst] --------
// One warp handles 4 edges: 8 lanes/edge, each lane moves 2 float4 (32 B).
// Lanes 0/8/16/24 load their edge's indices + dinv[dst]; three warp-wide
// shfls broadcast all four edges at once. Scatter uses vector reductions
// (red.global.add.v4.f32, no return value). 1.6M edges / 4 = 400000 warps
// = 50000 blocks of 256 threads exactly -> no tail guard needed.
#define SCATTER_BLOCKS (N_EDGES / 4 / 8)   // 50000
__global__ __launch_bounds__(256) void scatter_kernel(const void* __restrict__ eidx) {
    int warp_id = (blockIdx.x << 3) | (threadIdx.x >> 5);
    int lane = threadIdx.x & 31;
    int sub  = lane >> 3;                    // 0..3: which edge of the quad
    int j    = lane & 7;                     // this lane's pair of float4s
    int e = warp_id * 4 + sub;

    int src = 0, dst = 0;
    float norm = 0.f;
    if (j == 0) {                            // lanes 0,8,16,24 do the loads
        if (g_is64) {
            const long long* p = (const long long*)eidx;
            src = (int)__ldg(p + e);
            dst = (int)__ldg(p + N_EDGES + e);
        } else {
            const int* p = (const int*)eidx;
            src = __ldg(p + e);
            dst = __ldg(p + N_EDGES + e);
        }
        norm = g_dinv[dst];
    }
    const unsigned mask = 0xFFFFFFFFu;
    src  = __shfl_sync(mask, src,  sub << 3);
    dst  = __shfl_sync(mask, dst,  sub << 3);
    norm = __shfl_sync(mask, norm, sub << 3);

    const float4* hp = reinterpret_cast<const float4*>(g_h + (size_t)src * HID);
    float4 v0 = hp[2 * j];
    float4 v1 = hp[2 * j + 1];
    v0.x *= norm; v0.y *= norm; v0.z *= norm; v0.w *= norm;
    v1.x *= norm; v1.y *= norm; v1.z *= norm; v1.w *= norm;

    float* ap = g_agg + (size_t)dst * HID + j * 8;
    asm volatile("red.global.add.v4.f32 [%0], {%1,%2,%3,%4};"
                 :: "l"(ap), "f"(v0.x), "f"(v0.y), "f"(v0.z), "f"(v0.w)
                 : "memory");
    asm volatile("red.global.add.v4.f32 [%0], {%1,%2,%3,%4};"
                 :: "l"(ap + 4), "f"(v1.x), "f"(v1.y), "f"(v1.z), "f"(v1.w)
                 : "memory");
}

// -------- 6. self-loop + bias + relu + mean-pool accumulation --------
// batch is SORTED, so each thread walks a contiguous node chunk and flushes
// one atomic per graph transition. Block = (32 channel-pairs, 8 slices):
// each thread handles 2 channels via float2 loads, halving the issue count
// of the serial inner walk. Chunks are 4-aligned for vector batch loads.
#define POOL_BLOCKS 64
#define NSLICES (POOL_BLOCKS * 8)
__global__ void pool_kernel(const void* __restrict__ batch,
                            const float* __restrict__ b_conv) {
    const int c2 = threadIdx.x;          // 0..31 -> channels 2*c2, 2*c2+1
    const int slice = blockIdx.x * 8 + threadIdx.y;
    const int CHUNK = ((N_NODES + NSLICES - 1) / NSLICES + 3) & ~3;  // 4-aligned
    int start = slice * CHUNK;
    int end = min(start + CHUNK, N_NODES);
    if (start >= end) return;

    const int is64 = g_is64;
    const float2 bc = *reinterpret_cast<const float2*>(b_conv + 2 * c2);

    float2 acc = make_float2(0.f, 0.f);
    float cacc = 0.f;
    int cur = is64 ? (int)((const long long*)batch)[start]
                   : ((const int*)batch)[start];

    for (int i0 = start; i0 < end; i0 += 4) {
        int gid[4];
        if (is64) {
            longlong2 a = __ldg((const longlong2*)batch + i0 / 2);
            longlong2 b = __ldg((const longlong2*)batch + i0 / 2 + 1);
            gid[0] = (int)a.x; gid[1] = (int)a.y;
            gid[2] = (int)b.x; gid[3] = (int)b.y;
        } else {
            int4 a = __ldg((const int4*)batch + i0 / 4);
            gid[0] = a.x; gid[1] = a.y; gid[2] = a.z; gid[3] = a.w;
        }
        #pragma unroll
        for (int u = 0; u < 4; u++) {
            int i = i0 + u;
            if (i >= end) break;
            int g = gid[u];
            if (g != cur) {
                atomicAdd(&g_pooled[cur * HID + 2 * c2],     acc.x);
                atomicAdd(&g_pooled[cur * HID + 2 * c2 + 1], acc.y);
                if (c2 == 0) atomicAdd(&g_cnt[cur], cacc);
                acc = make_float2(0.f, 0.f); cacc = 0.f; cur = g;
            }
            // self-loop: h'[i]*dinv[i] == h[i]*dinv[i]^2
            const float di = g_dinv[i];
            float2 av = *reinterpret_cast<const float2*>(
                            g_agg + (size_t)i * HID + 2 * c2);
            float2 hv = *reinterpret_cast<const float2*>(
                            g_h + (size_t)i * HID + 2 * c2);
            acc.x += fmaxf(fmaf(hv.x, di, av.x) + bc.x, 0.f);
            acc.y += fmaxf(fmaf(hv.y, di, av.y) + bc.y, 0.f);
            cacc += 1.f;
        }
    }
    atomicAdd(&g_pooled[cur * HID + 2 * c2],     acc.x);
    atomicAdd(&g_pooled[cur * HID + 2 * c2 + 1], acc.y);
    if (c2 == 0) atomicAdd(&g_cnt[cur], cacc);
}

// -------- 7. out = (pooled / cnt) @ W_lin + b_lin --------
__global__ void final_kernel(const float* __restrict__ Wl,
                             const float* __restrict__ bl,
                             float* __restrict__ out) {
    __shared__ float Ws[HID * OUT_CH];  // 640 floats
    const int g = threadIdx.x;          // one graph per thread, 256 threads
    for (int i = g; i < HID * OUT_CH; i += 256) Ws[i] = Wl[i];
    __syncthreads();

    float inv = 1.f / fmaxf(g_cnt[g], 1.f);
    float p[HID];
    #pragma unroll
    for (int k = 0; k < HID; k++) p[k] = g_pooled[g * HID + k] * inv;

    #pragma unroll
    for (int o = 0; o < OUT_CH; o++) {
        float acc = bl[o];
        #pragma unroll
        for (int k = 0; k < HID; k++)
            acc = fmaf(p[k], Ws[k * OUT_CH + o], acc);
        out[g * OUT_CH + o] = acc;
    }
}

// -------- launch --------
extern "C" void kernel_launch(void* const* d_in, const int* in_sizes, int n_in,
                              void* d_out, int out_size) {
    const float* x    = (const float*)d_in[0];
    const void*  eidx = d_in[1];
    const void*  batch= d_in[2];
    const float* Wc   = (const float*)d_in[3];
    const float* bc   = (const float*)d_in[4];
    const float* Wl   = (const float*)d_in[5];
    const float* bl   = (const float*)d_in[6];
    float* out = (float*)d_out;

    zero_kernel<<<98, 256>>>((const unsigned int*)eidx);        // 25088 >= 25000
    degree_kernel<<<(N_EDGES / 4 + 255) / 256, 256>>>(eidx);    // 1563 blocks
    dinv_kernel<<<(N_NODES / 4 + 255) / 256, 256>>>();          // 98 blocks
    gemm1_kernel<<<N_NODES / 16, dim3(16, 16)>>>(x, Wc);        // 6250 blocks
    scatter_kernel<<<SCATTER_BLOCKS, 256>>>(eidx);              // 50000 blocks
    pool_kernel<<<POOL_BLOCKS, dim3(32, 8)>>>(batch, bc);
    final_kernel<<<1, 256>>>(Wl, bl, out);
}